// round 1
// baseline (speedup 1.0000x reference)
#include <cuda_runtime.h>
#include <math.h>

// Problem constants
#define NMAX   50000
#define EMAX   800000
#define HEADS  4
#define HID    64
#define QK     256        // HEADS*HID
#define OCT    832        // 3*QK + HID
#define NGRAPH 64
#define GDIM   256
#define NCLS   10

// ---------------- scratch (device globals; no runtime allocation) ----------------
__device__ __align__(16) float    g_q   [NMAX * QK];
__device__ __align__(16) float    g_k   [NMAX * QK];
__device__ __align__(16) float    g_v   [NMAX * QK];
__device__ __align__(16) float    g_skip[NMAX * HID];
__device__ __align__(16) float    g_agg [NMAX * QK];
__device__ __align__(16) float    g_h1  [NMAX * HID];
__device__ __align__(16) float    g_h2  [NMAX * HID];
__device__ __align__(16) float    g_sew [EMAX * HEADS];
__device__ __align__(16) unsigned g_menc[NMAX * HEADS];
__device__ __align__(16) float    g_z   [NMAX * HEADS];
__device__ __align__(16) float    g_Wc  [128 * OCT];
__device__ __align__(16) float    g_bc  [OCT];
__device__ __align__(16) float    g_gsum[NGRAPH * HID];
__device__ __align__(16) float    g_gcnt[NGRAPH];

// ---------------- helpers ----------------
__device__ __forceinline__ unsigned enc_f(float f) {
    int i = __float_as_int(f);
    return (i >= 0) ? ((unsigned)i | 0x80000000u) : ~(unsigned)i;
}
__device__ __forceinline__ float dec_f(unsigned u) {
    int i = (u & 0x80000000u) ? (int)(u & 0x7fffffffu) : ~(int)u;
    return __int_as_float(i);
}
__device__ __forceinline__ void red_add_v4(float* p, float a, float b, float c, float d) {
    asm volatile("red.global.add.v4.f32 [%0], {%1,%2,%3,%4};"
                 :: "l"(p), "f"(a), "f"(b), "f"(c), "f"(d) : "memory");
}

// ---------------- weight pack: Wc[K][832] = [Wq|Wk|Wv|Ws], bc[832] ----------------
__global__ void pack_w(const float* __restrict__ Wq, const float* __restrict__ bq,
                       const float* __restrict__ Wk, const float* __restrict__ bk,
                       const float* __restrict__ Wv, const float* __restrict__ bv,
                       const float* __restrict__ Ws, const float* __restrict__ bs, int K) {
    int idx = blockIdx.x * blockDim.x + threadIdx.x;
    int tot = K * OCT;
    if (idx < tot) {
        int k = idx / OCT, j = idx - k * OCT;
        float v;
        if      (j < 256) v = Wq[k * 256 + j];
        else if (j < 512) v = Wk[k * 256 + (j - 256)];
        else if (j < 768) v = Wv[k * 256 + (j - 512)];
        else              v = Ws[k * 64  + (j - 768)];
        g_Wc[idx] = v;
    }
    if (idx < OCT) {
        float b;
        if      (idx < 256) b = bq[idx];
        else if (idx < 512) b = bk[idx - 256];
        else if (idx < 768) b = bv[idx - 512];
        else                b = bs[idx - 768];
        g_bc[idx] = b;
    }
}

// ---------------- GEMM: C[N,832] = A[N,K] @ Wc[K,832] + bc ; routed to q/k/v/skip ----------------
__global__ void gemm_qkvs(const float* __restrict__ A, int N, int K) {
    __shared__ float As[16][64];
    __shared__ float Bs[16][64];
    int tx = threadIdx.x & 15, ty = threadIdx.x >> 4;
    int row0 = blockIdx.x * 64, col0 = blockIdx.y * 64;
    float acc[4][4] = {};
    for (int k0 = 0; k0 < K; k0 += 16) {
        {   // load A 64x16 (transposed into As[k][row])
            int r = threadIdx.x >> 2, c = (threadIdx.x & 3) << 2;
            float4 a = (row0 + r < N) ? *(const float4*)&A[(size_t)(row0 + r) * K + k0 + c]
                                      : make_float4(0.f, 0.f, 0.f, 0.f);
            As[c + 0][r] = a.x; As[c + 1][r] = a.y; As[c + 2][r] = a.z; As[c + 3][r] = a.w;
        }
        {   // load W 16x64
            int kk = threadIdx.x >> 4, j = (threadIdx.x & 15) << 2;
            float4 b = *(const float4*)&g_Wc[(size_t)(k0 + kk) * OCT + col0 + j];
            *(float4*)&Bs[kk][j] = b;
        }
        __syncthreads();
        #pragma unroll
        for (int kk = 0; kk < 16; kk++) {
            float4 a = *(const float4*)&As[kk][ty * 4];
            float4 b = *(const float4*)&Bs[kk][tx * 4];
            acc[0][0] += a.x * b.x; acc[0][1] += a.x * b.y; acc[0][2] += a.x * b.z; acc[0][3] += a.x * b.w;
            acc[1][0] += a.y * b.x; acc[1][1] += a.y * b.y; acc[1][2] += a.y * b.z; acc[1][3] += a.y * b.w;
            acc[2][0] += a.z * b.x; acc[2][1] += a.z * b.y; acc[2][2] += a.z * b.z; acc[2][3] += a.z * b.w;
            acc[3][0] += a.w * b.x; acc[3][1] += a.w * b.y; acc[3][2] += a.w * b.z; acc[3][3] += a.w * b.w;
        }
        __syncthreads();
    }
    #pragma unroll
    for (int i = 0; i < 4; i++) {
        int n = row0 + ty * 4 + i;
        if (n >= N) continue;
        #pragma unroll
        for (int j = 0; j < 4; j++) {
            int jc = col0 + tx * 4 + j;
            float val = acc[i][j] + g_bc[jc];
            if      (jc < 256) g_q   [(size_t)n * 256 + jc]        = val;
            else if (jc < 512) g_k   [(size_t)n * 256 + jc - 256]  = val;
            else if (jc < 768) g_v   [(size_t)n * 256 + jc - 512]  = val;
            else               g_skip[(size_t)n * 64  + jc - 768]  = val;
        }
    }
}

// ---------------- pass1: per-edge logits + segment max (warp per edge) ----------------
__global__ void edge_logits(const int* __restrict__ ei, int E) {
    int w    = (blockIdx.x * blockDim.x + threadIdx.x) >> 5;
    int lane = threadIdx.x & 31;
    if (w >= E) return;
    int src = ei[w], dst = ei[E + w];
    const float4* qd = (const float4*)&g_q[(size_t)dst * QK];
    const float4* ks = (const float4*)&g_k[(size_t)src * QK];
    float sv[2];
    #pragma unroll
    for (int it = 0; it < 2; it++) {
        int idx = it * 32 + lane;
        float4 a = qd[idx], b = ks[idx];
        float p = a.x * b.x + a.y * b.y + a.z * b.z + a.w * b.w;
        p += __shfl_xor_sync(0xffffffffu, p, 1);
        p += __shfl_xor_sync(0xffffffffu, p, 2);
        p += __shfl_xor_sync(0xffffffffu, p, 4);
        p += __shfl_xor_sync(0xffffffffu, p, 8);
        sv[it] = p * 0.125f;   // 1/sqrt(64)
    }
    if ((lane & 15) == 0) {
        int hb = lane >> 4;  // 0 or 1
        #pragma unroll
        for (int it = 0; it < 2; it++) {
            int h = it * 2 + hb;
            float val = sv[it];
            g_sew[(size_t)w * 4 + h] = val;
            atomicMax(&g_menc[(size_t)dst * 4 + h], enc_f(val));
        }
    }
}

// ---------------- pass2: exp(s - m) and segment sum z ----------------
__global__ void edge_exp(const int* __restrict__ ei, int E) {
    int e = blockIdx.x * blockDim.x + threadIdx.x;
    if (e >= E) return;
    int dst = ei[E + e];
    float4 s  = *(const float4*)&g_sew[(size_t)e * 4];
    uint4  mu = *(const uint4*)&g_menc[(size_t)dst * 4];
    float4 ev;
    ev.x = __expf(s.x - dec_f(mu.x));
    ev.y = __expf(s.y - dec_f(mu.y));
    ev.z = __expf(s.z - dec_f(mu.z));
    ev.w = __expf(s.w - dec_f(mu.w));
    *(float4*)&g_sew[(size_t)e * 4] = ev;
    red_add_v4(&g_z[(size_t)dst * 4], ev.x, ev.y, ev.z, ev.w);
}

// ---------------- pass3: agg[dst] += alpha * v[src] (warp per edge) ----------------
__global__ void edge_agg(const int* __restrict__ ei, int E) {
    int w    = (blockIdx.x * blockDim.x + threadIdx.x) >> 5;
    int lane = threadIdx.x & 31;
    if (w >= E) return;
    int src = ei[w], dst = ei[E + w];
    float4 evv = *(const float4*)&g_sew[(size_t)w * 4];
    float4 zz  = *(const float4*)&g_z[(size_t)dst * 4];
    float wgt[4] = { evv.x / zz.x, evv.y / zz.y, evv.z / zz.z, evv.w / zz.w };
    const float4* vs = (const float4*)&g_v[(size_t)src * QK];
    float* ap = &g_agg[(size_t)dst * QK];
    #pragma unroll
    for (int it = 0; it < 2; it++) {
        int idx = it * 32 + lane;
        float4 vv = vs[idx];
        float  ww = wgt[idx >> 4];
        red_add_v4(ap + idx * 4, vv.x * ww, vv.y * ww, vv.z * ww, vv.w * ww);
    }
}

// ---------------- finalize: relu(mean-over-heads + skip) ----------------
__global__ void finalize_conv(float* __restrict__ out, int N) {
    int idx = blockIdx.x * blockDim.x + threadIdx.x;
    if (idx >= N * HID) return;
    int n = idx >> 6, d = idx & 63;
    const float* ag = &g_agg[(size_t)n * QK];
    float v = 0.25f * (ag[d] + ag[64 + d] + ag[128 + d] + ag[192 + d])
              + g_skip[(size_t)n * HID + d];
    out[idx] = fmaxf(v, 0.f);
}

// ---------------- pool: per-graph mean of g_h2 (batch is sorted) ----------------
__global__ void pool_kernel(const int* __restrict__ batch, int N) {
    const int NPB = 256;
    int d = threadIdx.x;           // 0..63
    int n0 = blockIdx.x * NPB;
    int n1 = min(n0 + NPB, N);
    float acc = 0.f, cnt = 0.f;
    int cur = -1;
    for (int n = n0; n < n1; n++) {
        int g = batch[n];
        if (g != cur) {
            if (cur >= 0) {
                atomicAdd(&g_gsum[cur * HID + d], acc);
                if (d == 0) atomicAdd(&g_gcnt[cur], cnt);
            }
            cur = g; acc = 0.f; cnt = 0.f;
        }
        acc += g_h2[(size_t)n * HID + d];
        cnt += 1.f;
    }
    if (cur >= 0) {
        atomicAdd(&g_gsum[cur * HID + d], acc);
        if (d == 0) atomicAdd(&g_gcnt[cur], cnt);
    }
}

// ---------------- head: global MLP + concat + classifier (single block) ----------------
__global__ void head_kernel(const float* __restrict__ gf,
                            const float* __restrict__ gW1, const float* __restrict__ gb1,
                            const float* __restrict__ gW2, const float* __restrict__ gb2,
                            const float* __restrict__ hW1, const float* __restrict__ hb1,
                            const float* __restrict__ hW2, const float* __restrict__ hb2,
                            float* __restrict__ out) {
    __shared__ float sm_patch[NGRAPH * HID];
    __shared__ float sm_A[NGRAPH * HID];
    __shared__ float sm_B[NGRAPH * HID];
    int tid = threadIdx.x;

    // patch embedding
    for (int idx = tid; idx < NGRAPH * HID; idx += blockDim.x) {
        int g = idx >> 6;
        sm_patch[idx] = g_gsum[idx] / fmaxf(g_gcnt[g], 1.f);
    }
    __syncthreads();
    // g1 = relu(gf @ gW1 + gb1)   [64,64], K=256
    for (int idx = tid; idx < NGRAPH * HID; idx += blockDim.x) {
        int g = idx >> 6, j = idx & 63;
        float s = gb1[j];
        for (int k = 0; k < GDIM; k++) s += gf[g * GDIM + k] * gW1[k * HID + j];
        sm_A[idx] = fmaxf(s, 0.f);
    }
    __syncthreads();
    // g2 = relu(g1 @ gW2 + gb2)   K=64
    for (int idx = tid; idx < NGRAPH * HID; idx += blockDim.x) {
        int g = idx >> 6, j = idx & 63;
        float s = gb2[j];
        for (int k = 0; k < HID; k++) s += sm_A[g * HID + k] * gW2[k * HID + j];
        sm_B[idx] = fmaxf(s, 0.f);
    }
    __syncthreads();
    // hid = relu([patch, g2] @ hW1 + hb1)   K=128
    for (int idx = tid; idx < NGRAPH * HID; idx += blockDim.x) {
        int g = idx >> 6, j = idx & 63;
        float s = hb1[j];
        for (int k = 0; k < HID; k++) s += sm_patch[g * HID + k] * hW1[k * HID + j];
        for (int k = 0; k < HID; k++) s += sm_B[g * HID + k] * hW1[(HID + k) * HID + j];
        sm_A[idx] = fmaxf(s, 0.f);
    }
    __syncthreads();
    // out = hid @ hW2 + hb2   [64,10]
    for (int idx = tid; idx < NGRAPH * NCLS; idx += blockDim.x) {
        int g = idx / NCLS, j = idx - g * NCLS;
        float s = hb2[j];
        for (int k = 0; k < HID; k++) s += sm_A[g * HID + k] * hW2[k * NCLS + j];
        out[idx] = s;
    }
}

// ---------------- host orchestration ----------------
static void run_conv(const float* xin, int K, int N, int E, const int* ei,
                     const float* Wq, const float* bq, const float* Wk, const float* bk,
                     const float* Wv, const float* bv, const float* Ws, const float* bs,
                     float* hout,
                     void* menc_p, void* z_p, void* agg_p) {
    pack_w<<<(K * OCT + 255) / 256, 256>>>(Wq, bq, Wk, bk, Wv, bv, Ws, bs, K);
    dim3 gg((N + 63) / 64, OCT / 64);
    gemm_qkvs<<<gg, 256>>>(xin, N, K);
    cudaMemsetAsync(menc_p, 0, (size_t)N * HEADS * sizeof(unsigned), 0);
    cudaMemsetAsync(z_p,    0, (size_t)N * HEADS * sizeof(float), 0);
    cudaMemsetAsync(agg_p,  0, (size_t)N * QK * sizeof(float), 0);
    int ethreads = E * 32;
    edge_logits<<<(ethreads + 255) / 256, 256>>>(ei, E);
    edge_exp<<<(E + 255) / 256, 256>>>(ei, E);
    edge_agg<<<(ethreads + 255) / 256, 256>>>(ei, E);
    finalize_conv<<<(N * HID + 255) / 256, 256>>>(hout, N);
}

extern "C" void kernel_launch(void* const* d_in, const int* in_sizes, int n_in,
                              void* d_out, int out_size) {
    const float* x     = (const float*)d_in[0];
    const int*   ei    = (const int*)  d_in[1];
    const int*   batch = (const int*)  d_in[2];
    const float* gf    = (const float*)d_in[3];
    const float* c1[8]; for (int i = 0; i < 8; i++) c1[i] = (const float*)d_in[4 + i];
    const float* c2[8]; for (int i = 0; i < 8; i++) c2[i] = (const float*)d_in[12 + i];
    const float* gW1 = (const float*)d_in[20]; const float* gb1 = (const float*)d_in[21];
    const float* gW2 = (const float*)d_in[22]; const float* gb2 = (const float*)d_in[23];
    const float* hW1 = (const float*)d_in[24]; const float* hb1 = (const float*)d_in[25];
    const float* hW2 = (const float*)d_in[26]; const float* hb2 = (const float*)d_in[27];

    int N = in_sizes[0] / 128;
    int E = in_sizes[1] / 2;

    void *p_h1, *p_h2, *p_menc, *p_z, *p_agg, *p_gsum, *p_gcnt;
    cudaGetSymbolAddress(&p_h1,   g_h1);
    cudaGetSymbolAddress(&p_h2,   g_h2);
    cudaGetSymbolAddress(&p_menc, g_menc);
    cudaGetSymbolAddress(&p_z,    g_z);
    cudaGetSymbolAddress(&p_agg,  g_agg);
    cudaGetSymbolAddress(&p_gsum, g_gsum);
    cudaGetSymbolAddress(&p_gcnt, g_gcnt);

    // conv1 (in=128)
    run_conv(x, 128, N, E, ei,
             c1[0], c1[1], c1[2], c1[3], c1[4], c1[5], c1[6], c1[7],
             (float*)p_h1, p_menc, p_z, p_agg);
    // conv2 (in=64)
    run_conv((const float*)p_h1, 64, N, E, ei,
             c2[0], c2[1], c2[2], c2[3], c2[4], c2[5], c2[6], c2[7],
             (float*)p_h2, p_menc, p_z, p_agg);

    // pooling
    cudaMemsetAsync(p_gsum, 0, NGRAPH * HID * sizeof(float), 0);
    cudaMemsetAsync(p_gcnt, 0, NGRAPH * sizeof(float), 0);
    pool_kernel<<<(N + 255) / 256, HID>>>(batch, N);

    // head
    head_kernel<<<1, 256>>>(gf, gW1, gb1, gW2, gb2, hW1, hb1, hW2, hb2, (float*)d_out);
}

// round 2
// speedup vs baseline: 1.2185x; 1.2185x over previous
#include <cuda_runtime.h>
#include <math.h>

// Problem constants
#define NMAX   50000
#define EMAX   800000
#define HEADS  4
#define HID    64
#define QK     256        // HEADS*HID
#define OCT    832        // 3*QK + HID
#define NGRAPH 64
#define GDIM   256
#define NCLS   10

// ---------------- scratch (device globals; no runtime allocation) ----------------
__device__ __align__(16) float    g_q   [NMAX * QK];
__device__ __align__(16) float    g_k   [NMAX * QK];
__device__ __align__(16) float    g_v   [NMAX * QK];
__device__ __align__(16) float    g_skip[NMAX * HID];
__device__ __align__(16) float    g_agg [NMAX * HID];   // head-mean folded in: only HID per node
__device__ __align__(16) float    g_h1  [NMAX * HID];
__device__ __align__(16) float    g_h2  [NMAX * HID];
__device__ __align__(16) float    g_sew [EMAX * HEADS];
__device__ __align__(16) unsigned g_menc[NMAX * HEADS];
__device__ __align__(16) float    g_z   [NMAX * HEADS];
__device__ __align__(16) float    g_Wc  [128 * OCT];
__device__ __align__(16) float    g_bc  [OCT];
__device__ __align__(16) float    g_gsum[NGRAPH * HID];
__device__ __align__(16) float    g_gcnt[NGRAPH];

// ---------------- helpers ----------------
__device__ __forceinline__ unsigned enc_f(float f) {
    int i = __float_as_int(f);
    return (i >= 0) ? ((unsigned)i | 0x80000000u) : ~(unsigned)i;
}
__device__ __forceinline__ float dec_f(unsigned u) {
    int i = (u & 0x80000000u) ? (int)(u & 0x7fffffffu) : ~(int)u;
    return __int_as_float(i);
}
__device__ __forceinline__ void red_add_v4(float* p, float a, float b, float c, float d) {
    asm volatile("red.global.add.v4.f32 [%0], {%1,%2,%3,%4};"
                 :: "l"(p), "f"(a), "f"(b), "f"(c), "f"(d) : "memory");
}

// ---------------- weight pack: Wc[K][832] = [Wq|Wk|Wv|Ws], bc[832] ----------------
__global__ void pack_w(const float* __restrict__ Wq, const float* __restrict__ bq,
                       const float* __restrict__ Wk, const float* __restrict__ bk,
                       const float* __restrict__ Wv, const float* __restrict__ bv,
                       const float* __restrict__ Ws, const float* __restrict__ bs, int K) {
    int idx = blockIdx.x * blockDim.x + threadIdx.x;
    int tot = K * OCT;
    if (idx < tot) {
        int k = idx / OCT, j = idx - k * OCT;
        float v;
        if      (j < 256) v = Wq[k * 256 + j];
        else if (j < 512) v = Wk[k * 256 + (j - 256)];
        else if (j < 768) v = Wv[k * 256 + (j - 512)];
        else              v = Ws[k * 64  + (j - 768)];
        g_Wc[idx] = v;
    }
    if (idx < OCT) {
        float b;
        if      (idx < 256) b = bq[idx];
        else if (idx < 512) b = bk[idx - 256];
        else if (idx < 768) b = bv[idx - 512];
        else                b = bs[idx - 768];
        g_bc[idx] = b;
    }
}

// ---------------- GEMM: C[N,832] = A[N,K] @ Wc[K,832] + bc ; routed to q/k/v/skip ----
// BM=128, BN=64, BK=16, 256 threads, 8x4 per-thread micro-tile (FFMA-bound).
__global__ void gemm_qkvs(const float* __restrict__ A, int N, int K) {
    __shared__ float As[16][132];   // [k][m], padded to kill store conflicts, 16B-aligned rows
    __shared__ float Bs[16][64];    // [k][n]
    int t  = threadIdx.x;
    int tx = t & 15, ty = t >> 4;
    int row0 = blockIdx.x * 128, col0 = blockIdx.y * 64;
    float acc[8][4] = {};
    for (int k0 = 0; k0 < K; k0 += 16) {
        #pragma unroll
        for (int ii = 0; ii < 2; ii++) {      // A: 128x16 = 512 float4, 2 per thread
            int i = t + ii * 256;
            int r = i >> 2, cg = (i & 3) << 2;
            int gr = row0 + r;
            float4 a = (gr < N) ? *(const float4*)&A[(size_t)gr * K + k0 + cg]
                                : make_float4(0.f, 0.f, 0.f, 0.f);
            As[cg + 0][r] = a.x; As[cg + 1][r] = a.y; As[cg + 2][r] = a.z; As[cg + 3][r] = a.w;
        }
        {                                      // B: 16x64 = 256 float4, 1 per thread
            int kk = t >> 4, j = (t & 15) << 2;
            *(float4*)&Bs[kk][j] = *(const float4*)&g_Wc[(size_t)(k0 + kk) * OCT + col0 + j];
        }
        __syncthreads();
        #pragma unroll
        for (int kk = 0; kk < 16; kk++) {
            float4 a0 = *(const float4*)&As[kk][ty * 8];
            float4 a1 = *(const float4*)&As[kk][ty * 8 + 4];
            float4 b  = *(const float4*)&Bs[kk][tx * 4];
            float av[8] = {a0.x, a0.y, a0.z, a0.w, a1.x, a1.y, a1.z, a1.w};
            float bv[4] = {b.x, b.y, b.z, b.w};
            #pragma unroll
            for (int i = 0; i < 8; i++)
                #pragma unroll
                for (int j = 0; j < 4; j++)
                    acc[i][j] += av[i] * bv[j];
        }
        __syncthreads();
    }
    #pragma unroll
    for (int i = 0; i < 8; i++) {
        int n = row0 + ty * 8 + i;
        if (n >= N) continue;
        #pragma unroll
        for (int j = 0; j < 4; j++) {
            int jc = col0 + tx * 4 + j;
            float val = acc[i][j] + g_bc[jc];
            if      (jc < 256) g_q   [(size_t)n * 256 + jc]        = val;
            else if (jc < 512) g_k   [(size_t)n * 256 + jc - 256]  = val;
            else if (jc < 768) g_v   [(size_t)n * 256 + jc - 512]  = val;
            else               g_skip[(size_t)n * 64  + jc - 768]  = val;
        }
    }
}

// ---------------- pass1: per-edge logits + segment max (warp per edge) ----------------
__global__ void edge_logits(const int* __restrict__ ei, int E) {
    int w    = (blockIdx.x * blockDim.x + threadIdx.x) >> 5;
    int lane = threadIdx.x & 31;
    if (w >= E) return;
    int src = ei[w], dst = ei[E + w];
    const float4* qd = (const float4*)&g_q[(size_t)dst * QK];
    const float4* ks = (const float4*)&g_k[(size_t)src * QK];
    float sv[2];
    #pragma unroll
    for (int it = 0; it < 2; it++) {
        int idx = it * 32 + lane;
        float4 a = qd[idx], b = ks[idx];
        float p = a.x * b.x + a.y * b.y + a.z * b.z + a.w * b.w;
        p += __shfl_xor_sync(0xffffffffu, p, 1);
        p += __shfl_xor_sync(0xffffffffu, p, 2);
        p += __shfl_xor_sync(0xffffffffu, p, 4);
        p += __shfl_xor_sync(0xffffffffu, p, 8);
        sv[it] = p * 0.125f;   // 1/sqrt(64)
    }
    if ((lane & 15) == 0) {
        int hb = lane >> 4;  // 0 or 1
        #pragma unroll
        for (int it = 0; it < 2; it++) {
            int h = it * 2 + hb;
            float val = sv[it];
            g_sew[(size_t)w * 4 + h] = val;
            atomicMax(&g_menc[(size_t)dst * 4 + h], enc_f(val));
        }
    }
}

// ---------------- pass2: exp(s - m) and segment sum z ----------------
__global__ void edge_exp(const int* __restrict__ ei, int E) {
    int e = blockIdx.x * blockDim.x + threadIdx.x;
    if (e >= E) return;
    int dst = ei[E + e];
    float4 s  = *(const float4*)&g_sew[(size_t)e * 4];
    uint4  mu = *(const uint4*)&g_menc[(size_t)dst * 4];
    float4 ev;
    ev.x = __expf(s.x - dec_f(mu.x));
    ev.y = __expf(s.y - dec_f(mu.y));
    ev.z = __expf(s.z - dec_f(mu.z));
    ev.w = __expf(s.w - dec_f(mu.w));
    *(float4*)&g_sew[(size_t)e * 4] = ev;
    red_add_v4(&g_z[(size_t)dst * 4], ev.x, ev.y, ev.z, ev.w);
}

// ---------------- pass3 (head-mean folded): agg64[dst] += sum_h (alpha_h/4)*v[src][h] ----
// 16 lanes per edge; each lane owns 4 output dims, one red.v4 per lane.
__global__ void edge_agg(const int* __restrict__ ei, int E) {
    int gid  = blockIdx.x * blockDim.x + threadIdx.x;
    int e    = gid >> 4;
    int l    = gid & 15;
    if (e >= E) return;
    int src = ei[e], dst = ei[E + e];
    float4 ev = *(const float4*)&g_sew[(size_t)e * 4];
    float4 zz = *(const float4*)&g_z[(size_t)dst * 4];
    float w0 = 0.25f * ev.x / zz.x;
    float w1 = 0.25f * ev.y / zz.y;
    float w2 = 0.25f * ev.z / zz.z;
    float w3 = 0.25f * ev.w / zz.w;
    const float* vb = &g_v[(size_t)src * QK + l * 4];
    float4 a = *(const float4*)(vb);
    float4 b = *(const float4*)(vb + 64);
    float4 c = *(const float4*)(vb + 128);
    float4 d = *(const float4*)(vb + 192);
    float o0 = w0 * a.x + w1 * b.x + w2 * c.x + w3 * d.x;
    float o1 = w0 * a.y + w1 * b.y + w2 * c.y + w3 * d.y;
    float o2 = w0 * a.z + w1 * b.z + w2 * c.z + w3 * d.z;
    float o3 = w0 * a.w + w1 * b.w + w2 * c.w + w3 * d.w;
    red_add_v4(&g_agg[(size_t)dst * HID + l * 4], o0, o1, o2, o3);
}

// ---------------- finalize: relu(agg + skip) ----------------
__global__ void finalize_conv(float* __restrict__ out, int N) {
    int idx = blockIdx.x * blockDim.x + threadIdx.x;   // over N*16 float4s
    if (idx >= N * (HID / 4)) return;
    float4 ag = *(const float4*)&g_agg[(size_t)idx * 4];
    float4 sk = *(const float4*)&g_skip[(size_t)idx * 4];
    float4 o;
    o.x = fmaxf(ag.x + sk.x, 0.f);
    o.y = fmaxf(ag.y + sk.y, 0.f);
    o.z = fmaxf(ag.z + sk.z, 0.f);
    o.w = fmaxf(ag.w + sk.w, 0.f);
    *(float4*)&out[(size_t)idx * 4] = o;
}

// ---------------- pool: per-graph mean of g_h2 (batch is sorted) ----------------
__global__ void pool_kernel(const int* __restrict__ batch, int N) {
    const int NPB = 256;
    int d = threadIdx.x;           // 0..63
    int n0 = blockIdx.x * NPB;
    int n1 = min(n0 + NPB, N);
    float acc = 0.f, cnt = 0.f;
    int cur = -1;
    for (int n = n0; n < n1; n++) {
        int g = batch[n];
        if (g != cur) {
            if (cur >= 0) {
                atomicAdd(&g_gsum[cur * HID + d], acc);
                if (d == 0) atomicAdd(&g_gcnt[cur], cnt);
            }
            cur = g; acc = 0.f; cnt = 0.f;
        }
        acc += g_h2[(size_t)n * HID + d];
        cnt += 1.f;
    }
    if (cur >= 0) {
        atomicAdd(&g_gsum[cur * HID + d], acc);
        if (d == 0) atomicAdd(&g_gcnt[cur], cnt);
    }
}

// ---------------- head: global MLP + concat + classifier (single block) ----------------
__global__ void head_kernel(const float* __restrict__ gf,
                            const float* __restrict__ gW1, const float* __restrict__ gb1,
                            const float* __restrict__ gW2, const float* __restrict__ gb2,
                            const float* __restrict__ hW1, const float* __restrict__ hb1,
                            const float* __restrict__ hW2, const float* __restrict__ hb2,
                            float* __restrict__ out) {
    __shared__ float sm_patch[NGRAPH * HID];
    __shared__ float sm_A[NGRAPH * HID];
    __shared__ float sm_B[NGRAPH * HID];
    int tid = threadIdx.x;

    for (int idx = tid; idx < NGRAPH * HID; idx += blockDim.x) {
        int g = idx >> 6;
        sm_patch[idx] = g_gsum[idx] / fmaxf(g_gcnt[g], 1.f);
    }
    __syncthreads();
    for (int idx = tid; idx < NGRAPH * HID; idx += blockDim.x) {
        int g = idx >> 6, j = idx & 63;
        float s = gb1[j];
        for (int k = 0; k < GDIM; k++) s += gf[g * GDIM + k] * gW1[k * HID + j];
        sm_A[idx] = fmaxf(s, 0.f);
    }
    __syncthreads();
    for (int idx = tid; idx < NGRAPH * HID; idx += blockDim.x) {
        int g = idx >> 6, j = idx & 63;
        float s = gb2[j];
        for (int k = 0; k < HID; k++) s += sm_A[g * HID + k] * gW2[k * HID + j];
        sm_B[idx] = fmaxf(s, 0.f);
    }
    __syncthreads();
    for (int idx = tid; idx < NGRAPH * HID; idx += blockDim.x) {
        int g = idx >> 6, j = idx & 63;
        float s = hb1[j];
        for (int k = 0; k < HID; k++) s += sm_patch[g * HID + k] * hW1[k * HID + j];
        for (int k = 0; k < HID; k++) s += sm_B[g * HID + k] * hW1[(HID + k) * HID + j];
        sm_A[idx] = fmaxf(s, 0.f);
    }
    __syncthreads();
    for (int idx = tid; idx < NGRAPH * NCLS; idx += blockDim.x) {
        int g = idx / NCLS, j = idx - g * NCLS;
        float s = hb2[j];
        for (int k = 0; k < HID; k++) s += sm_A[g * HID + k] * hW2[k * NCLS + j];
        out[idx] = s;
    }
}

// ---------------- host orchestration ----------------
static void run_conv(const float* xin, int K, int N, int E, const int* ei,
                     const float* Wq, const float* bq, const float* Wk, const float* bk,
                     const float* Wv, const float* bv, const float* Ws, const float* bs,
                     float* hout,
                     void* menc_p, void* z_p, void* agg_p) {
    pack_w<<<(K * OCT + 255) / 256, 256>>>(Wq, bq, Wk, bk, Wv, bv, Ws, bs, K);
    cudaMemsetAsync(menc_p, 0, (size_t)N * HEADS * sizeof(unsigned), 0);
    cudaMemsetAsync(z_p,    0, (size_t)N * HEADS * sizeof(float), 0);
    cudaMemsetAsync(agg_p,  0, (size_t)N * HID * sizeof(float), 0);
    dim3 gg((N + 127) / 128, OCT / 64);
    gemm_qkvs<<<gg, 256>>>(xin, N, K);
    int lthreads = E * 32;
    edge_logits<<<(lthreads + 255) / 256, 256>>>(ei, E);
    edge_exp<<<(E + 255) / 256, 256>>>(ei, E);
    int athreads = E * 16;
    edge_agg<<<(athreads + 255) / 256, 256>>>(ei, E);
    finalize_conv<<<(N * (HID / 4) + 255) / 256, 256>>>(hout, N);
}

extern "C" void kernel_launch(void* const* d_in, const int* in_sizes, int n_in,
                              void* d_out, int out_size) {
    const float* x     = (const float*)d_in[0];
    const int*   ei    = (const int*)  d_in[1];
    const int*   batch = (const int*)  d_in[2];
    const float* gf    = (const float*)d_in[3];
    const float* c1[8]; for (int i = 0; i < 8; i++) c1[i] = (const float*)d_in[4 + i];
    const float* c2[8]; for (int i = 0; i < 8; i++) c2[i] = (const float*)d_in[12 + i];
    const float* gW1 = (const float*)d_in[20]; const float* gb1 = (const float*)d_in[21];
    const float* gW2 = (const float*)d_in[22]; const float* gb2 = (const float*)d_in[23];
    const float* hW1 = (const float*)d_in[24]; const float* hb1 = (const float*)d_in[25];
    const float* hW2 = (const float*)d_in[26]; const float* hb2 = (const float*)d_in[27];

    int N = in_sizes[0] / 128;
    int E = in_sizes[1] / 2;

    void *p_h1, *p_h2, *p_menc, *p_z, *p_agg, *p_gsum, *p_gcnt;
    cudaGetSymbolAddress(&p_h1,   g_h1);
    cudaGetSymbolAddress(&p_h2,   g_h2);
    cudaGetSymbolAddress(&p_menc, g_menc);
    cudaGetSymbolAddress(&p_z,    g_z);
    cudaGetSymbolAddress(&p_agg,  g_agg);
    cudaGetSymbolAddress(&p_gsum, g_gsum);
    cudaGetSymbolAddress(&p_gcnt, g_gcnt);

    // conv1 (in=128)
    run_conv(x, 128, N, E, ei,
             c1[0], c1[1], c1[2], c1[3], c1[4], c1[5], c1[6], c1[7],
             (float*)p_h1, p_menc, p_z, p_agg);
    // conv2 (in=64)
    run_conv((const float*)p_h1, 64, N, E, ei,
             c2[0], c2[1], c2[2], c2[3], c2[4], c2[5], c2[6], c2[7],
             (float*)p_h2, p_menc, p_z, p_agg);

    // pooling
    cudaMemsetAsync(p_gsum, 0, NGRAPH * HID * sizeof(float), 0);
    cudaMemsetAsync(p_gcnt, 0, NGRAPH * sizeof(float), 0);
    pool_kernel<<<(N + 255) / 256, HID>>>(batch, N);

    // head
    head_kernel<<<1, 256>>>(gf, gW1, gb1, gW2, gb2, hW1, hb1, hW2, hb2, (float*)d_out);
}